// round 1
// baseline (speedup 1.0000x reference)
#include <cuda_runtime.h>
#include <math.h>

#define Bq 8
#define Cc 192
#define HH 128
#define WW 128
#define HWsz (HH*WW)      // 16384
#define C3 (3*Cc)         // 576
#define NHEADS 4
#define Dh 48             // C / heads

// ---- scratch (device globals: no cudaMalloc allowed) ----
__device__ float g_qkv[(long)Bq*C3*HWsz];    // after 1x1 conv
__device__ float g_qkvdw[(long)Bq*C3*HWsz];  // after depthwise 3x3
__device__ float g_norms[Bq*2*Cc];           // sum of squares for q,k rows
__device__ float g_gram[Bq*NHEADS*Dh*Dh];    // raw gram -> attn (in place)
__device__ float g_M[Bq*Cc*Cc];              // proj_w folded with attn

// ---------------- zero init ----------------
__global__ void zero_kernel(float* p, int n) {
    int i = blockIdx.x * blockDim.x + threadIdx.x;
    if (i < n) p[i] = 0.f;
}

// ---------------- tiled SGEMM with bias ----------------
// C[m,n] = sum_k A[m,k]*B[k,n] + bias[m], batched via blockIdx.z with strides.
// Requires N % BN == 0 and K % BK == 0 (true here); M guarded.
template<int BM, int BN, int BK, int TM, int TN>
__global__ void sgemm_bias_kernel(const float* __restrict__ A, long sA,
                                  const float* __restrict__ B, long sB,
                                  float* __restrict__ C, long sC,
                                  const float* __restrict__ bias,
                                  int M, int N, int K)
{
    constexpr int THREADS = (BM/TM)*(BN/TN);
    __shared__ float As[BK][BM+4];
    __shared__ float Bs[BK][BN+4];

    const int bz = blockIdx.z;
    const float* Ab = A + (long)bz * sA;
    const float* Bb = B + (long)bz * sB;
    float* Cb = C + (long)bz * sC;

    const int m0 = blockIdx.y * BM;
    const int n0 = blockIdx.x * BN;
    const int tid = threadIdx.x;
    const int tm = tid / (BN/TN);
    const int tn = tid % (BN/TN);

    float acc[TM][TN];
    #pragma unroll
    for (int i = 0; i < TM; i++)
        #pragma unroll
        for (int j = 0; j < TN; j++) acc[i][j] = 0.f;

    for (int k0 = 0; k0 < K; k0 += BK) {
        // load A tile (BM x BK), transposed into As[k][m]
        #pragma unroll
        for (int f = tid; f < BM*BK/4; f += THREADS) {
            int m  = f / (BK/4);
            int k4 = f % (BK/4);
            float4 v = make_float4(0.f,0.f,0.f,0.f);
            if (m0 + m < M)
                v = *(const float4*)(Ab + (long)(m0+m)*K + k0 + k4*4);
            As[k4*4+0][m] = v.x;
            As[k4*4+1][m] = v.y;
            As[k4*4+2][m] = v.z;
            As[k4*4+3][m] = v.w;
        }
        // load B tile (BK x BN)
        #pragma unroll
        for (int f = tid; f < BK*BN/4; f += THREADS) {
            int k  = f / (BN/4);
            int n4 = f % (BN/4);
            float4 v = *(const float4*)(Bb + (long)(k0+k)*N + n0 + n4*4);
            Bs[k][n4*4+0] = v.x;
            Bs[k][n4*4+1] = v.y;
            Bs[k][n4*4+2] = v.z;
            Bs[k][n4*4+3] = v.w;
        }
        __syncthreads();

        #pragma unroll
        for (int kk = 0; kk < BK; kk++) {
            float a[TM], b[TN];
            #pragma unroll
            for (int i = 0; i < TM; i++) a[i] = As[kk][tm*TM + i];
            #pragma unroll
            for (int j = 0; j < TN; j++) b[j] = Bs[kk][tn*TN + j];
            #pragma unroll
            for (int i = 0; i < TM; i++)
                #pragma unroll
                for (int j = 0; j < TN; j++)
                    acc[i][j] = fmaf(a[i], b[j], acc[i][j]);
        }
        __syncthreads();
    }

    #pragma unroll
    for (int i = 0; i < TM; i++) {
        int m = m0 + tm*TM + i;
        if (m >= M) continue;
        float bv = bias ? bias[m] : 0.f;
        #pragma unroll
        for (int j = 0; j < TN; j += 4) {
            float4 v;
            v.x = acc[i][j+0] + bv;
            v.y = acc[i][j+1] + bv;
            v.z = acc[i][j+2] + bv;
            v.w = acc[i][j+3] + bv;
            *(float4*)(Cb + (long)m*N + n0 + tn*TN + j) = v;
        }
    }
}

// ---------------- depthwise 3x3 + sumsq(q,k) ----------------
__global__ void dwconv_kernel(const float* __restrict__ in,
                              const float* __restrict__ w,
                              const float* __restrict__ bias,
                              float* __restrict__ out,
                              float* __restrict__ norms)
{
    const int bc = blockIdx.x;            // b*C3 + ch
    const int b  = bc / C3;
    const int ch = bc % C3;
    const int p  = blockIdx.y * 256 + threadIdx.x;
    const int y  = p / WW;
    const int x  = p % WW;

    const float* ip = in + (long)bc * HWsz;
    const float* wp = w + ch * 9;

    float acc = bias[ch];
    #pragma unroll
    for (int ky = 0; ky < 3; ky++) {
        int yy = y + ky - 1;
        if (yy < 0 || yy >= HH) continue;
        #pragma unroll
        for (int kx = 0; kx < 3; kx++) {
            int xx = x + kx - 1;
            if (xx < 0 || xx >= WW) continue;
            acc = fmaf(wp[ky*3+kx], ip[yy*WW + xx], acc);
        }
    }
    out[(long)bc * HWsz + p] = acc;

    // sum of squares for q (ch<192) and k (192<=ch<384) channel rows
    float sq = (ch < 2*Cc) ? acc * acc : 0.f;
    __shared__ float red[256];
    red[threadIdx.x] = sq;
    __syncthreads();
    #pragma unroll
    for (int s = 128; s > 0; s >>= 1) {
        if (threadIdx.x < s) red[threadIdx.x] += red[threadIdx.x + s];
        __syncthreads();
    }
    if (threadIdx.x == 0 && ch < 2*Cc)
        atomicAdd(&norms[b*2*Cc + ch], red[0]);
}

// ---------------- gram: G[d,e] = sum_n q[d,n]*k[e,n], split over n ----------------
#define GRAM_SPLITS 64
__global__ void gram_kernel(const float* __restrict__ qk, float* __restrict__ gram)
{
    const int bh = blockIdx.x;            // b*NHEADS + h
    const int split = blockIdx.y;
    const int b = bh / NHEADS, h = bh % NHEADS;

    const float* qp = qk + ((long)b*C3 + h*Dh) * HWsz;
    const float* kp = qk + ((long)b*C3 + Cc + h*Dh) * HWsz;

    __shared__ float qs[Dh][34];
    __shared__ float ks[Dh][34];

    const int tid = threadIdx.x;
    const int ty = tid / 16;   // 0..15 -> rows ty*3..ty*3+2
    const int tx = tid % 16;

    float acc[3][3];
    #pragma unroll
    for (int i = 0; i < 3; i++)
        #pragma unroll
        for (int j = 0; j < 3; j++) acc[i][j] = 0.f;

    const int chunk = HWsz / GRAM_SPLITS;        // 256
    const int nbase = split * chunk;

    for (int t = 0; t < chunk; t += 32) {
        for (int f = tid; f < Dh*32; f += 256) {
            int r = f / 32, cn = f % 32;
            qs[r][cn] = qp[(long)r*HWsz + nbase + t + cn];
            ks[r][cn] = kp[(long)r*HWsz + nbase + t + cn];
        }
        __syncthreads();
        #pragma unroll
        for (int n = 0; n < 32; n++) {
            float a0 = qs[ty*3+0][n], a1 = qs[ty*3+1][n], a2 = qs[ty*3+2][n];
            float b0 = ks[tx*3+0][n], b1 = ks[tx*3+1][n], b2 = ks[tx*3+2][n];
            acc[0][0] = fmaf(a0,b0,acc[0][0]); acc[0][1] = fmaf(a0,b1,acc[0][1]); acc[0][2] = fmaf(a0,b2,acc[0][2]);
            acc[1][0] = fmaf(a1,b0,acc[1][0]); acc[1][1] = fmaf(a1,b1,acc[1][1]); acc[1][2] = fmaf(a1,b2,acc[1][2]);
            acc[2][0] = fmaf(a2,b0,acc[2][0]); acc[2][1] = fmaf(a2,b1,acc[2][1]); acc[2][2] = fmaf(a2,b2,acc[2][2]);
        }
        __syncthreads();
    }

    float* gp = gram + (long)bh * Dh * Dh;
    #pragma unroll
    for (int i = 0; i < 3; i++)
        #pragma unroll
        for (int j = 0; j < 3; j++)
            atomicAdd(&gp[(ty*3+i)*Dh + tx*3+j], acc[i][j]);
}

// ---------------- normalize + temperature + softmax (in place on gram) --------
__global__ void attn_softmax_kernel(const float* __restrict__ temp,
                                    const float* __restrict__ norms,
                                    float* __restrict__ gram)
{
    int idx = blockIdx.x * blockDim.x + threadIdx.x;  // one row (b,h,d)
    if (idx >= Bq*NHEADS*Dh) return;
    int d  = idx % Dh;
    int bh = idx / Dh;
    int h = bh % NHEADS, b = bh / NHEADS;

    float nq = fmaxf(sqrtf(norms[b*2*Cc + h*Dh + d]), 1e-12f);
    float t = temp[h];
    float* row = gram + (long)bh*Dh*Dh + d*Dh;

    float vals[Dh];
    float mx = -1e30f;
    #pragma unroll
    for (int e = 0; e < Dh; e++) {
        float nk = fmaxf(sqrtf(norms[b*2*Cc + Cc + h*Dh + e]), 1e-12f);
        float v = row[e] / (nq * nk) * t;
        vals[e] = v;
        mx = fmaxf(mx, v);
    }
    float s = 0.f;
    #pragma unroll
    for (int e = 0; e < Dh; e++) { vals[e] = expf(vals[e] - mx); s += vals[e]; }
    float inv = 1.f / s;
    #pragma unroll
    for (int e = 0; e < Dh; e++) row[e] = vals[e] * inv;
}

// ---------------- fold proj into attn: M[b,o,h*48+e] = sum_dl pw[o,h*48+dl]*attn[dl,e]
__global__ void fold_kernel(const float* __restrict__ proj_w,
                            const float* __restrict__ gram,
                            float* __restrict__ Mout)
{
    int idx = blockIdx.x * 256 + threadIdx.x;
    if (idx >= Bq*Cc*Cc) return;
    int he = idx % Cc;
    int o  = (idx / Cc) % Cc;
    int b  = idx / (Cc*Cc);
    int h = he / Dh, e = he % Dh;
    const float* attn = gram + ((long)(b*NHEADS + h)) * Dh * Dh;
    const float* pw = proj_w + (long)o*Cc + h*Dh;
    float s = 0.f;
    #pragma unroll
    for (int dl = 0; dl < Dh; dl++)
        s = fmaf(pw[dl], attn[dl*Dh + e], s);
    Mout[idx] = s;
}

// ---------------- launch ----------------
extern "C" void kernel_launch(void* const* d_in, const int* in_sizes, int n_in,
                              void* d_out, int out_size)
{
    const float* x      = (const float*)d_in[0];
    const float* qkv_w  = (const float*)d_in[1];
    const float* qkv_b  = (const float*)d_in[2];
    const float* dw_w   = (const float*)d_in[3];
    const float* dw_b   = (const float*)d_in[4];
    const float* temp   = (const float*)d_in[5];
    const float* proj_w = (const float*)d_in[6];
    const float* proj_b = (const float*)d_in[7];
    float* out = (float*)d_out;

    float *p_qkv, *p_qkvdw, *p_norms, *p_gram, *p_M;
    cudaGetSymbolAddress((void**)&p_qkv,   g_qkv);
    cudaGetSymbolAddress((void**)&p_qkvdw, g_qkvdw);
    cudaGetSymbolAddress((void**)&p_norms, g_norms);
    cudaGetSymbolAddress((void**)&p_gram,  g_gram);
    cudaGetSymbolAddress((void**)&p_M,     g_M);

    // zero accumulators
    zero_kernel<<<(Bq*2*Cc + 255)/256, 256>>>(p_norms, Bq*2*Cc);
    zero_kernel<<<(Bq*NHEADS*Dh*Dh + 255)/256, 256>>>(p_gram, Bq*NHEADS*Dh*Dh);

    // GEMM1: qkv = qkv_w @ x  (per batch)
    {
        dim3 grid(HWsz/128, (C3 + 127)/128, Bq);
        sgemm_bias_kernel<128,128,16,8,8><<<grid, 256>>>(
            qkv_w, 0L,
            x, (long)Cc*HWsz,
            p_qkv, (long)C3*HWsz,
            qkv_b, C3, HWsz, Cc);
    }

    // depthwise 3x3 + sumsq
    {
        dim3 grid(Bq*C3, HWsz/256);
        dwconv_kernel<<<grid, 256>>>(p_qkv, dw_w, dw_b, p_qkvdw, p_norms);
    }

    // gram matrices
    {
        dim3 grid(Bq*NHEADS, GRAM_SPLITS);
        gram_kernel<<<grid, 256>>>(p_qkvdw, p_gram);
    }

    // softmax (in place)
    attn_softmax_kernel<<<(Bq*NHEADS*Dh + 255)/256, 256>>>(temp, p_norms, p_gram);

    // fold proj_w with attn
    fold_kernel<<<(Bq*Cc*Cc + 255)/256, 256>>>(proj_w, p_gram, p_M);

    // GEMM4: out = M[b] @ v + proj_b
    {
        dim3 grid(HWsz/128, (Cc + 127)/128, Bq);
        sgemm_bias_kernel<128,128,16,8,8><<<grid, 256>>>(
            p_M, (long)Cc*Cc,
            p_qkvdw + (long)2*Cc*HWsz, (long)C3*HWsz,
            out, (long)Cc*HWsz,
            proj_b, Cc, HWsz, Cc);
    }
}

// round 2
// speedup vs baseline: 2.4441x; 2.4441x over previous
#include <cuda_runtime.h>
#include <math.h>

#define Bq 8
#define Cc 192
#define HH 128
#define WW 128
#define HWsz (HH*WW)      // 16384
#define C3 (3*Cc)         // 576
#define NHEADS 4
#define Dh 48             // C / heads

// ---- scratch (device globals: no cudaMalloc allowed) ----
__device__ float g_qkv[(long)Bq*C3*HWsz];    // after 1x1 conv
__device__ float g_qkvdw[(long)Bq*C3*HWsz];  // after depthwise 3x3
__device__ float g_norms[Bq*2*Cc];           // sum of squares for q,k rows
__device__ float g_gram[Bq*NHEADS*Dh*Dh];    // raw gram -> attn (in place)
__device__ float g_M[Bq*Cc*Cc];              // proj_w folded with attn

// ---------------- zero init ----------------
__global__ void zero_kernel(float* p0, int n0, float* p1, int n1) {
    int i = blockIdx.x * blockDim.x + threadIdx.x;
    if (i < n0) p0[i] = 0.f;
    if (i < n1) p1[i] = 0.f;
}

// ---------------- tf32 helpers ----------------
__device__ __forceinline__ unsigned f2tf32(float x) {
    unsigned r;
    asm("cvt.rna.tf32.f32 %0, %1;" : "=r"(r) : "f"(x));
    return r;
}

// ---------------- tf32 tensor-core GEMM with bias ----------------
// C[m,n] = sum_k A[m,k]*B[k,n] + bias[m], batched via blockIdx.z with strides.
// BM=128, BN=128, BK=16. 256 threads = 8 warps in 4(M) x 2(N) layout.
// Warp tile 32x64 via m16n8k8 tf32 mma (2 m-frags x 8 n-frags).
#define GBM 128
#define GBN 128
#define GBK 16
#define GPAD 136
__global__ void __launch_bounds__(256)
tf32_gemm_bias_kernel(const float* __restrict__ A, long sA,
                      const float* __restrict__ B, long sB,
                      float* __restrict__ C, long sC,
                      const float* __restrict__ bias,
                      int M, int N, int K)
{
    __shared__ unsigned As[GBK][GPAD];   // [k][m], tf32 bits
    __shared__ unsigned Bs[GBK][GPAD];   // [k][n], tf32 bits

    const int bz = blockIdx.z;
    const float* Ab = A + (long)bz * sA;
    const float* Bb = B + (long)bz * sB;
    float* Cb = C + (long)bz * sC;

    const int m0 = blockIdx.y * GBM;
    const int n0 = blockIdx.x * GBN;
    const int tid  = threadIdx.x;
    const int wid  = tid >> 5;
    const int lane = tid & 31;
    const int gid  = lane >> 2;   // group id 0..7
    const int tig  = lane & 3;    // thread in group 0..3
    const int wm = (wid & 3) * 32;   // warp M offset
    const int wn = (wid >> 2) * 64;  // warp N offset

    float acc[2][8][4];
    #pragma unroll
    for (int i = 0; i < 2; i++)
        #pragma unroll
        for (int j = 0; j < 8; j++)
            #pragma unroll
            for (int q = 0; q < 4; q++) acc[i][j][q] = 0.f;

    for (int k0 = 0; k0 < K; k0 += GBK) {
        // load A tile (BM x BK) transposed -> As[k][m]
        #pragma unroll
        for (int f = tid; f < GBM*GBK/4; f += 256) {
            int m  = f / (GBK/4);
            int k4 = f % (GBK/4);
            float4 v = make_float4(0.f,0.f,0.f,0.f);
            if (m0 + m < M)
                v = *(const float4*)(Ab + (long)(m0+m)*K + k0 + k4*4);
            As[k4*4+0][m] = f2tf32(v.x);
            As[k4*4+1][m] = f2tf32(v.y);
            As[k4*4+2][m] = f2tf32(v.z);
            As[k4*4+3][m] = f2tf32(v.w);
        }
        // load B tile (BK x BN) -> Bs[k][n]
        #pragma unroll
        for (int f = tid; f < GBK*GBN/4; f += 256) {
            int k  = f / (GBN/4);
            int n4 = f % (GBN/4);
            float4 v = *(const float4*)(Bb + (long)(k0+k)*N + n0 + n4*4);
            Bs[k][n4*4+0] = f2tf32(v.x);
            Bs[k][n4*4+1] = f2tf32(v.y);
            Bs[k][n4*4+2] = f2tf32(v.z);
            Bs[k][n4*4+3] = f2tf32(v.w);
        }
        __syncthreads();

        #pragma unroll
        for (int ks = 0; ks < GBK; ks += 8) {
            unsigned a[2][4];
            #pragma unroll
            for (int mi = 0; mi < 2; mi++) {
                int mr = wm + mi*16;
                a[mi][0] = As[ks+tig  ][mr + gid];
                a[mi][1] = As[ks+tig  ][mr + gid + 8];
                a[mi][2] = As[ks+tig+4][mr + gid];
                a[mi][3] = As[ks+tig+4][mr + gid + 8];
            }
            #pragma unroll
            for (int ni = 0; ni < 8; ni++) {
                int nb = wn + ni*8;
                unsigned b0 = Bs[ks+tig  ][nb + gid];
                unsigned b1 = Bs[ks+tig+4][nb + gid];
                #pragma unroll
                for (int mi = 0; mi < 2; mi++) {
                    asm volatile(
                        "mma.sync.aligned.m16n8k8.row.col.f32.tf32.tf32.f32 "
                        "{%0,%1,%2,%3}, {%4,%5,%6,%7}, {%8,%9}, {%0,%1,%2,%3};"
                        : "+f"(acc[mi][ni][0]), "+f"(acc[mi][ni][1]),
                          "+f"(acc[mi][ni][2]), "+f"(acc[mi][ni][3])
                        : "r"(a[mi][0]), "r"(a[mi][1]), "r"(a[mi][2]), "r"(a[mi][3]),
                          "r"(b0), "r"(b1));
                }
            }
        }
        __syncthreads();
    }

    // epilogue: c0,c1 at (row=gid, col=tig*2, tig*2+1); c2,c3 at row=gid+8
    #pragma unroll
    for (int mi = 0; mi < 2; mi++) {
        int r0 = m0 + wm + mi*16 + gid;
        int r1 = r0 + 8;
        float bv0 = (r0 < M && bias) ? bias[r0] : 0.f;
        float bv1 = (r1 < M && bias) ? bias[r1] : 0.f;
        #pragma unroll
        for (int ni = 0; ni < 8; ni++) {
            int col = n0 + wn + ni*8 + tig*2;
            if (r0 < M) {
                float2 v; v.x = acc[mi][ni][0] + bv0; v.y = acc[mi][ni][1] + bv0;
                *(float2*)(Cb + (long)r0*N + col) = v;
            }
            if (r1 < M) {
                float2 v; v.x = acc[mi][ni][2] + bv1; v.y = acc[mi][ni][3] + bv1;
                *(float2*)(Cb + (long)r1*N + col) = v;
            }
        }
    }
}

// ---------------- depthwise 3x3 + sumsq(q,k), 4 pixels/thread ----------------
__global__ void __launch_bounds__(256)
dwconv_kernel(const float* __restrict__ in,
              const float* __restrict__ w,
              const float* __restrict__ bias,
              float* __restrict__ out,
              float* __restrict__ norms)
{
    const int bc = blockIdx.x;            // b*C3 + ch
    const int b  = bc / C3;
    const int ch = bc % C3;
    const int tid = threadIdx.x;
    const int t = blockIdx.y * 256 + tid; // 0..4095
    const int y  = t >> 5;                // 32 threads per row (128/4)
    const int x  = (t & 31) << 2;         // multiple of 4

    const float* ip = in + (long)bc * HWsz;
    float wv[9];
    #pragma unroll
    for (int i = 0; i < 9; i++) wv[i] = w[ch*9 + i];

    float row[3][6];
    #pragma unroll
    for (int r = 0; r < 3; r++) {
        int yy = y + r - 1;
        if (yy >= 0 && yy < HH) {
            const float* rp = ip + yy*WW;
            float4 v = *(const float4*)(rp + x);
            row[r][1] = v.x; row[r][2] = v.y; row[r][3] = v.z; row[r][4] = v.w;
            row[r][0] = (x > 0)       ? rp[x-1] : 0.f;
            row[r][5] = (x + 4 < WW)  ? rp[x+4] : 0.f;
        } else {
            #pragma unroll
            for (int c = 0; c < 6; c++) row[r][c] = 0.f;
        }
    }

    const float bv = bias[ch];
    float o[4];
    #pragma unroll
    for (int j = 0; j < 4; j++) {
        float acc = bv;
        #pragma unroll
        for (int r = 0; r < 3; r++) {
            acc = fmaf(wv[r*3+0], row[r][j+0], acc);
            acc = fmaf(wv[r*3+1], row[r][j+1], acc);
            acc = fmaf(wv[r*3+2], row[r][j+2], acc);
        }
        o[j] = acc;
    }
    float4 ov; ov.x = o[0]; ov.y = o[1]; ov.z = o[2]; ov.w = o[3];
    *(float4*)(out + (long)bc * HWsz + y*WW + x) = ov;

    if (ch < 2*Cc) {
        float sq = o[0]*o[0] + o[1]*o[1] + o[2]*o[2] + o[3]*o[3];
        #pragma unroll
        for (int s = 16; s > 0; s >>= 1)
            sq += __shfl_xor_sync(0xFFFFFFFFu, sq, s);
        __shared__ float wred[8];
        if ((tid & 31) == 0) wred[tid >> 5] = sq;
        __syncthreads();
        if (tid == 0) {
            float s = 0.f;
            #pragma unroll
            for (int i = 0; i < 8; i++) s += wred[i];
            atomicAdd(&norms[b*2*Cc + ch], s);
        }
    }
}

// ---------------- gram: G[d,e] = sum_n q[d,n]*k[e,n], split over n ----------------
#define GRAM_SPLITS 64
__global__ void gram_kernel(const float* __restrict__ qk, float* __restrict__ gram)
{
    const int bh = blockIdx.x;            // b*NHEADS + h
    const int split = blockIdx.y;
    const int b = bh / NHEADS, h = bh % NHEADS;

    const float* qp = qk + ((long)b*C3 + h*Dh) * HWsz;
    const float* kp = qk + ((long)b*C3 + Cc + h*Dh) * HWsz;

    __shared__ float qs[Dh][34];
    __shared__ float ks[Dh][34];

    const int tid = threadIdx.x;
    const int ty = tid / 16;
    const int tx = tid % 16;

    float acc[3][3];
    #pragma unroll
    for (int i = 0; i < 3; i++)
        #pragma unroll
        for (int j = 0; j < 3; j++) acc[i][j] = 0.f;

    const int chunk = HWsz / GRAM_SPLITS;        // 256
    const int nbase = split * chunk;

    for (int t = 0; t < chunk; t += 32) {
        for (int f = tid; f < Dh*32; f += 256) {
            int r = f / 32, cn = f % 32;
            qs[r][cn] = qp[(long)r*HWsz + nbase + t + cn];
            ks[r][cn] = kp[(long)r*HWsz + nbase + t + cn];
        }
        __syncthreads();
        #pragma unroll
        for (int n = 0; n < 32; n++) {
            float a0 = qs[ty*3+0][n], a1 = qs[ty*3+1][n], a2 = qs[ty*3+2][n];
            float b0 = ks[tx*3+0][n], b1 = ks[tx*3+1][n], b2 = ks[tx*3+2][n];
            acc[0][0] = fmaf(a0,b0,acc[0][0]); acc[0][1] = fmaf(a0,b1,acc[0][1]); acc[0][2] = fmaf(a0,b2,acc[0][2]);
            acc[1][0] = fmaf(a1,b0,acc[1][0]); acc[1][1] = fmaf(a1,b1,acc[1][1]); acc[1][2] = fmaf(a1,b2,acc[1][2]);
            acc[2][0] = fmaf(a2,b0,acc[2][0]); acc[2][1] = fmaf(a2,b1,acc[2][1]); acc[2][2] = fmaf(a2,b2,acc[2][2]);
        }
        __syncthreads();
    }

    float* gp = gram + (long)bh * Dh * Dh;
    #pragma unroll
    for (int i = 0; i < 3; i++)
        #pragma unroll
        for (int j = 0; j < 3; j++)
            atomicAdd(&gp[(ty*3+i)*Dh + tx*3+j], acc[i][j]);
}

// ---------------- normalize + temperature + softmax (in place on gram) --------
__global__ void attn_softmax_kernel(const float* __restrict__ temp,
                                    const float* __restrict__ norms,
                                    float* __restrict__ gram)
{
    int idx = blockIdx.x * blockDim.x + threadIdx.x;  // one row (b,h,d)
    if (idx >= Bq*NHEADS*Dh) return;
    int d  = idx % Dh;
    int bh = idx / Dh;
    int h = bh % NHEADS, b = bh / NHEADS;

    float nq = fmaxf(sqrtf(norms[b*2*Cc + h*Dh + d]), 1e-12f);
    float t = temp[h];
    float* row = gram + (long)bh*Dh*Dh + d*Dh;

    float vals[Dh];
    float mx = -1e30f;
    #pragma unroll
    for (int e = 0; e < Dh; e++) {
        float nk = fmaxf(sqrtf(norms[b*2*Cc + Cc + h*Dh + e]), 1e-12f);
        float v = row[e] / (nq * nk) * t;
        vals[e] = v;
        mx = fmaxf(mx, v);
    }
    float s = 0.f;
    #pragma unroll
    for (int e = 0; e < Dh; e++) { vals[e] = expf(vals[e] - mx); s += vals[e]; }
    float inv = 1.f / s;
    #pragma unroll
    for (int e = 0; e < Dh; e++) row[e] = vals[e] * inv;
}

// ---------------- fold proj into attn: M[b,o,h*48+e] = sum_dl pw[o,h*48+dl]*attn[dl,e]
__global__ void fold_kernel(const float* __restrict__ proj_w,
                            const float* __restrict__ gram,
                            float* __restrict__ Mout)
{
    int idx = blockIdx.x * 256 + threadIdx.x;
    if (idx >= Bq*Cc*Cc) return;
    int he = idx % Cc;
    int o  = (idx / Cc) % Cc;
    int b  = idx / (Cc*Cc);
    int h = he / Dh, e = he % Dh;
    const float* attn = gram + ((long)(b*NHEADS + h)) * Dh * Dh;
    const float* pw = proj_w + (long)o*Cc + h*Dh;
    float s = 0.f;
    #pragma unroll
    for (int dl = 0; dl < Dh; dl++)
        s = fmaf(pw[dl], attn[dl*Dh + e], s);
    Mout[idx] = s;
}

// ---------------- launch ----------------
extern "C" void kernel_launch(void* const* d_in, const int* in_sizes, int n_in,
                              void* d_out, int out_size)
{
    const float* x      = (const float*)d_in[0];
    const float* qkv_w  = (const float*)d_in[1];
    const float* qkv_b  = (const float*)d_in[2];
    const float* dw_w   = (const float*)d_in[3];
    const float* dw_b   = (const float*)d_in[4];
    const float* temp   = (const float*)d_in[5];
    const float* proj_w = (const float*)d_in[6];
    const float* proj_b = (const float*)d_in[7];
    float* out = (float*)d_out;

    float *p_qkv, *p_qkvdw, *p_norms, *p_gram, *p_M;
    cudaGetSymbolAddress((void**)&p_qkv,   g_qkv);
    cudaGetSymbolAddress((void**)&p_qkvdw, g_qkvdw);
    cudaGetSymbolAddress((void**)&p_norms, g_norms);
    cudaGetSymbolAddress((void**)&p_gram,  g_gram);
    cudaGetSymbolAddress((void**)&p_M,     g_M);

    // zero accumulators (one launch)
    zero_kernel<<<(Bq*NHEADS*Dh*Dh + 255)/256, 256>>>(
        p_norms, Bq*2*Cc, p_gram, Bq*NHEADS*Dh*Dh);

    // GEMM1: qkv = qkv_w @ x  (per batch), tf32 tensor cores
    {
        dim3 grid(HWsz/GBN, (C3 + GBM - 1)/GBM, Bq);
        tf32_gemm_bias_kernel<<<grid, 256>>>(
            qkv_w, 0L,
            x, (long)Cc*HWsz,
            p_qkv, (long)C3*HWsz,
            qkv_b, C3, HWsz, Cc);
    }

    // depthwise 3x3 + sumsq (4 px/thread)
    {
        dim3 grid(Bq*C3, HWsz/1024);
        dwconv_kernel<<<grid, 256>>>(p_qkv, dw_w, dw_b, p_qkvdw, p_norms);
    }

    // gram matrices
    {
        dim3 grid(Bq*NHEADS, GRAM_SPLITS);
        gram_kernel<<<grid, 256>>>(p_qkvdw, p_gram);
    }

    // softmax (in place)
    attn_softmax_kernel<<<(Bq*NHEADS*Dh + 255)/256, 256>>>(temp, p_norms, p_gram);

    // fold proj_w with attn
    fold_kernel<<<(Bq*Cc*Cc + 255)/256, 256>>>(proj_w, p_gram, p_M);

    // GEMM4: out = M[b] @ v + proj_b, tf32 tensor cores
    {
        dim3 grid(HWsz/GBN, (Cc + GBM - 1)/GBM, Bq);
        tf32_gemm_bias_kernel<<<grid, 256>>>(
            p_M, (long)Cc*Cc,
            p_qkvdw + (long)2*Cc*HWsz, (long)C3*HWsz,
            out, (long)Cc*HWsz,
            proj_b, Cc, HWsz, Cc);
    }
}